// round 16
// baseline (speedup 1.0000x reference)
#include <cuda_runtime.h>
#include <cstdint>
#include <cmath>
#include <cstring>

#define N_NODES 10000
#define N_EDGES 100000
#define IN1_DIM 288
#define IN2_DIM 9
#define W_DIM   480
#define OUT_DIM 1632

// slot tables for the warp-cooperative stage 1 (validated: rel_err 1.1e-7)
struct TPTab {
  float cgs[256][5];
  unsigned short dst[256];
};

// ---------------------------------------------------------------------------
// HOST: exact numpy default_rng(42) replay (validated R7..R14).
// ---------------------------------------------------------------------------
typedef unsigned __int128 u128_t;
struct HostPcg {
  u128_t st, inc;
  void step() {
    const u128_t M = ((u128_t)2549297995355413924ULL << 64) | 4865540595714422341ULL;
    st = st * M + inc;
  }
  uint64_t n64() {
    step();
    uint64_t hi = (uint64_t)(st >> 64), lo = (uint64_t)st;
    unsigned rot = (unsigned)(st >> 122);
    uint64_t x = hi ^ lo;
    return (x >> rot) | (x << ((64u - rot) & 63u));
  }
  double nd() { return (double)(n64() >> 11) * (1.0 / 9007199254740992.0); }
};

static const int tD1[15] = {1,1,1,3,3,3,3,3,3,5,5,5,5,5,5};
static const int tD2[15] = {1,3,5,1,3,3,3,5,5,1,3,3,5,5,5};
static const int tD3[15] = {1,3,5,3,1,3,5,3,5,5,3,5,1,3,5};
static const int tROWB[15] = {0,1,2,3,6,9,12,15,18,21,26,31,36,41,46};

static void build_tab(TPTab& T) {
  uint32_t pool[4];
  {
    uint32_t hc = 0x43b0d7e5u;
    auto h = [&hc](uint32_t v) -> uint32_t {
      v ^= hc; hc *= 0x931e8875u; v *= hc; v ^= v >> 16; return v;
    };
    auto mix = [](uint32_t x, uint32_t y) -> uint32_t {
      uint32_t r = (x * 0xca01f9ddu) - (y * 0x4973f715u);
      r ^= r >> 16;
      return r;
    };
    pool[0] = h(42u); pool[1] = h(0u); pool[2] = h(0u); pool[3] = h(0u);
    for (int s = 0; s < 4; ++s)
      for (int d = 0; d < 4; ++d)
        if (s != d) pool[d] = mix(pool[d], h(pool[s]));
  }
  uint64_t sw[4];
  {
    uint32_t hc = 0x8b51f9ddu;
    uint32_t w32[8];
    for (int i = 0; i < 8; ++i) {
      uint32_t v = pool[i & 3];
      v ^= hc; hc *= 0x58f38dedu; v *= hc; v ^= v >> 16;
      w32[i] = v;
    }
    for (int k = 0; k < 4; ++k)
      sw[k] = (uint64_t)w32[2 * k] | ((uint64_t)w32[2 * k + 1] << 32);
  }
  HostPcg g;
  {
    u128_t initstate = ((u128_t)sw[0] << 64) | sw[1];
    u128_t initseq   = ((u128_t)sw[2] << 64) | sw[3];
    g.st = 0; g.inc = (initseq << 1) | 1;
    g.step(); g.st += initstate; g.step();
  }

  double zwi[256], zfi[256]; uint64_t zki[256];
  {
    const double m = 4503599627370496.0, r = 3.6541528853610088;
    double f = exp(-0.5 * r * r);
    double v = r * f + sqrt(1.5707963267948966) * erfc(r * 0.7071067811865476);
    double q = v / f, dn = r, tn = r;
    zki[0] = (uint64_t)((dn / q) * m);  zki[1] = 0;
    zwi[0] = q / m;  zwi[255] = dn / m;
    zfi[0] = 1.0;    zfi[255] = f;
    for (int i = 254; i >= 1; --i) {
      dn = sqrt(-2.0 * log(v / dn + exp(-0.5 * dn * dn)));
      zki[i + 1] = (uint64_t)((dn / tn) * m);
      tn = dn;
      zfi[i] = exp(-0.5 * dn * dn);
      zwi[i] = dn / m;
    }
  }
  auto stdnorm = [&]() -> double {
    const double r = 3.6541528853610088, inv_r = 0.27366123732975828;
    for (;;) {
      uint64_t rr = g.n64();
      int idx = (int)(rr & 0xff);
      rr >>= 8;
      int sign = (int)(rr & 1);
      uint64_t rabs = (rr >> 1) & 0x000fffffffffffffULL;
      double x = (double)rabs * zwi[idx];
      if (sign) x = -x;
      if (rabs < zki[idx]) return x;
      if (idx == 0) {
        double xx, yy;
        do {
          xx = -inv_r * log1p(-g.nd());
          yy = -log1p(-g.nd());
        } while (yy + yy <= xx * xx);
        return ((rabs >> 8) & 1) ? -(r + xx) : (r + xx);
      }
      if ((zfi[idx - 1] - zfi[idx]) * g.nd() + zfi[idx] < exp(-0.5 * x * x))
        return x;
    }
  };

  float cgpw[15][125];
  for (int t = 0; t < 15; ++t) {
    int d1 = tD1[t], d2 = tD2[t], d3 = tD3[t], sz = d1 * d2 * d3;
    unsigned char mk[125]; int any = 0;
    for (int q = 0; q < sz; ++q) { mk[q] = (g.nd() < 0.3) ? 1 : 0; any |= mk[q]; }
    if (!any) mk[0] = 1;
    float pw = (float)(1.0 / sqrt((double)(d1 * d2)));
    for (int q = 0; q < sz; ++q) {
      float v = (float)stdnorm();
      cgpw[t][q] = mk[q] ? (v * pw) : 0.0f;
    }
  }

  memset(&T, 0, sizeof(T));
  for (int s = 0; s < 256; ++s) T.dst[s] = 408;
  const int gA[3] = {0, 3, 9};
  const int gB[6] = {1, 4, 5, 6, 10, 11};
  const int gC[6] = {2, 7, 8, 12, 13, 14};
  auto fill = [&](const int* grp, int ng, int slot) {
    for (int gi = 0; gi < ng; ++gi) {
      int t = grp[gi], d1 = tD1[t], d2 = tD2[t], d3 = tD3[t];
      for (int i = 0; i < d1; ++i)
        for (int k = 0; k < d3; ++k) {
          for (int j = 0; j < d2; ++j)
            T.cgs[slot][j] = cgpw[t][(i * d2 + j) * d3 + k];
          T.dst[slot] = (unsigned short)((tROWB[t] + i) * 8 + k);
          ++slot;
        }
    }
  };
  fill(gA, 3, 0); fill(gB, 6, 64); fill(gC, 6, 160);
}

// ---------------------------------------------------------------------------
// Device scratch. g_cursor zero at load; hist adds, scatter subs back to 0.
// ---------------------------------------------------------------------------
__device__ int g_row_ptr[N_NODES + 1];
__device__ int g_cursor[N_NODES];
__device__ int g_edge_ids[N_EDGES];

__global__ void k_hist(const int* __restrict__ dst) {
  int e = blockIdx.x * blockDim.x + threadIdx.x;
  if (e < N_EDGES) atomicAdd(&g_cursor[dst[e]], 1);
}

__global__ void k_scan() {
  __shared__ int s_wsum[32];
  __shared__ int s_carry;
  const int tid = threadIdx.x, lane = tid & 31, w = tid >> 5;
  if (tid == 0) s_carry = 0;
  __syncthreads();
  for (int base = 0; base < N_NODES; base += 1024) {
    int i = base + tid;
    int v = (i < N_NODES) ? g_cursor[i] : 0;
    int x = v;
#pragma unroll
    for (int d = 1; d < 32; d <<= 1) {
      int y = __shfl_up_sync(0xffffffffu, x, d);
      if (lane >= d) x += y;
    }
    if (lane == 31) s_wsum[w] = x;
    __syncthreads();
    if (w == 0) {
      int z = s_wsum[lane];
#pragma unroll
      for (int d = 1; d < 32; d <<= 1) {
        int y = __shfl_up_sync(0xffffffffu, z, d);
        if (lane >= d) z += y;
      }
      s_wsum[lane] = z;
    }
    __syncthreads();
    int warp_excl = (w == 0) ? 0 : s_wsum[w - 1];
    int excl = s_carry + warp_excl + (x - v);
    if (i < N_NODES) g_row_ptr[i] = excl;
    __syncthreads();
    if (tid == 0) s_carry += s_wsum[31];
    __syncthreads();
  }
  if (tid == 0) g_row_ptr[N_NODES] = s_carry;
}

__global__ void k_scatter(const int* __restrict__ dst) {
  int e = blockIdx.x * blockDim.x + threadIdx.x;
  if (e < N_EDGES) {
    int d = dst[e];
    int pos = atomicSub(&g_cursor[d], 1) - 1;
    g_edge_ids[g_row_ptr[d] + pos] = e;
  }
}

// ---------------------------------------------------------------------------
// cp.async helpers
// ---------------------------------------------------------------------------
__device__ __forceinline__ uint32_t smem_u32(const void* p) {
  return (uint32_t)__cvta_generic_to_shared(p);
}
#define CP16(D, S) asm volatile("cp.async.cg.shared.global [%0], [%1], 16;" :: "r"(D), "l"(S))
#define CP4(D, S)  asm volatile("cp.async.ca.shared.global [%0], [%1], 4;"  :: "r"(D), "l"(S))
#define CPCOMMIT() asm volatile("cp.async.commit_group;" ::: "memory")
#define CPWAIT1()  asm volatile("cp.async.wait_group 1;" ::: "memory")

// ---------------------------------------------------------------------------
// Main kernel: warp per node. w/b prefetched one edge ahead via cp.async into
// a 2-stage per-warp smem ring (no dest registers, natural overlap). a (the
// lane-dependent L2 gather) is register-double-buffered. Edge ids/srcs
// preloaded lane-parallel and broadcast via shfl.
// ---------------------------------------------------------------------------
#define S2_1(AB, RB, KB, WI, DD, AA) { float t0 = 0.f;                         \
  _Pragma("unroll") for (int i = 0; i < (DD); ++i)                             \
    t0 = fmaf(AA[(AB) + i], cw[((RB) + i) * 8], t0);                           \
  acc[(KB)] = fmaf(wv[(WI)], t0, acc[(KB)]); }

#define S2_3(AB, RB, KB, WI, DD, AA) { float t0 = 0.f, t1 = 0.f, t2 = 0.f;     \
  _Pragma("unroll") for (int i = 0; i < (DD); ++i) {                           \
    float4 cv = *(const float4*)&cw[((RB) + i) * 8];                           \
    float ai = AA[(AB) + i];                                                   \
    t0 = fmaf(ai, cv.x, t0); t1 = fmaf(ai, cv.y, t1); t2 = fmaf(ai, cv.z, t2); } \
  acc[(KB)]     = fmaf(wv[(WI)], t0, acc[(KB)]);                               \
  acc[(KB) + 1] = fmaf(wv[(WI)], t1, acc[(KB) + 1]);                           \
  acc[(KB) + 2] = fmaf(wv[(WI)], t2, acc[(KB) + 2]); }

#define S2_5(AB, RB, KB, WI, DD, AA) {                                         \
  float t0 = 0.f, t1 = 0.f, t2 = 0.f, t3 = 0.f, t4 = 0.f;                      \
  _Pragma("unroll") for (int i = 0; i < (DD); ++i) {                           \
    float4 cv = *(const float4*)&cw[((RB) + i) * 8];                           \
    float c4 = cw[((RB) + i) * 8 + 4];                                         \
    float ai = AA[(AB) + i];                                                   \
    t0 = fmaf(ai, cv.x, t0); t1 = fmaf(ai, cv.y, t1); t2 = fmaf(ai, cv.z, t2); \
    t3 = fmaf(ai, cv.w, t3); t4 = fmaf(ai, c4, t4); }                          \
  acc[(KB)]     = fmaf(wv[(WI)], t0, acc[(KB)]);                               \
  acc[(KB) + 1] = fmaf(wv[(WI)], t1, acc[(KB) + 1]);                           \
  acc[(KB) + 2] = fmaf(wv[(WI)], t2, acc[(KB) + 2]);                           \
  acc[(KB) + 3] = fmaf(wv[(WI)], t3, acc[(KB) + 3]);                           \
  acc[(KB) + 4] = fmaf(wv[(WI)], t4, acc[(KB) + 4]); }

#define STO(OFF, DD, KB)                                                       \
  _Pragma("unroll") for (int k = 0; k < (DD); ++k)                             \
    O[(OFF) + lane * (DD) + k] = acc[(KB) + k];

#define LOAD_A(AA, S)                                                          \
  { const float* A_ = in1 + (size_t)(S) * IN1_DIM;                             \
    AA[0] = A_[lane];                                                          \
    { const float* p = A_ + 32 + lane * 3;  AA[1] = p[0]; AA[2] = p[1]; AA[3] = p[2]; } \
    { const float* p = A_ + 128 + lane * 5; AA[4] = p[0]; AA[5] = p[1]; AA[6] = p[2]; AA[7] = p[3]; AA[8] = p[4]; } }

// issue cp.asyncs for edge E into ring stage ST (w: 120 float4, b: 9 floats)
#define ISSUE_CP(E, ST) {                                                      \
  const char* Wg = (const char*)(wt + (size_t)(E) * W_DIM);                    \
  uint32_t wb = w_sm + (ST) * (480 * 4);                                       \
  CP16(wb + lane * 16,          Wg + lane * 16);                               \
  CP16(wb + (lane + 32) * 16,   Wg + (lane + 32) * 16);                        \
  CP16(wb + (lane + 64) * 16,   Wg + (lane + 64) * 16);                        \
  if (lane < 24) { CP16(wb + (lane + 96) * 16, Wg + (lane + 96) * 16); }       \
  if (lane < 9) {                                                              \
    CP4(b_sm + (ST) * 48 + lane * 4,                                           \
        (const char*)(in2 + (size_t)(E) * IN2_DIM) + lane * 4);                \
  }                                                                            \
}

// edge index T -> (edge id, src): shfl broadcast for T<32, direct load beyond
#define GET_ES(T, EV, SV)                                                      \
  if ((T) < 32) {                                                              \
    EV = __shfl_sync(0xffffffffu, myE, (T));                                   \
    SV = __shfl_sync(0xffffffffu, myS, (T));                                   \
  } else {                                                                     \
    EV = g_edge_ids[beg + (T)];                                                \
    SV = src[EV];                                                              \
  }

// One pipelined edge (uses ring stage ST for current payload):
#define EDGE_BODY(aC, aN, ST)                                                  \
  {                                                                            \
    if (t + 1 < deg) {                                                         \
      int eN, sN;                                                              \
      GET_ES(t + 1, eN, sN);                                                   \
      ISSUE_CP(eN, (ST) ^ 1);                                                  \
      LOAD_A(aN, sN);                                                          \
    }                                                                          \
    CPCOMMIT();                                                                \
    CPWAIT1();                                                                 \
    __syncwarp();                                                              \
    float b[9];                                                                \
    { const float* BS = &s_b[w][(ST) * 12];                                    \
      _Pragma("unroll") for (int j = 0; j < 9; ++j) b[j] = BS[j]; }            \
    cw[d0]  = A0c0 * b[0];                                                     \
    cw[d1_] = A1c0 * b[0];                                                     \
    cw[d2_] = fmaf(B0c2, b[3], fmaf(B0c1, b[2], B0c0 * b[1]));                 \
    cw[d3_] = fmaf(B1c2, b[3], fmaf(B1c1, b[2], B1c0 * b[1]));                 \
    cw[d4_] = fmaf(B2c2, b[3], fmaf(B2c1, b[2], B2c0 * b[1]));                 \
    cw[d5_] = fmaf(C0c4, b[8], fmaf(C0c3, b[7], fmaf(C0c2, b[6], fmaf(C0c1, b[5], C0c0 * b[4])))); \
    cw[d6_] = fmaf(C1c4, b[8], fmaf(C1c3, b[7], fmaf(C1c2, b[6], fmaf(C1c1, b[5], C1c0 * b[4])))); \
    cw[d7_] = fmaf(C2c4, b[8], fmaf(C2c3, b[7], fmaf(C2c2, b[6], fmaf(C2c1, b[5], C2c0 * b[4])))); \
    __syncwarp();                                                              \
    float wv[15];                                                              \
    { const float* WS = &s_w[w][(ST) * 480];                                   \
      _Pragma("unroll") for (int q = 0; q < 15; ++q) wv[q] = WS[q * 32 + lane]; } \
    S2_1(0, 0, 0, 0, 1, aC);                                                   \
    S2_3(0, 1, 1, 1, 1, aC);                                                   \
    S2_5(0, 2, 4, 2, 1, aC);                                                   \
    S2_3(1, 3, 9, 3, 3, aC);                                                   \
    S2_1(1, 6, 12, 4, 3, aC);                                                  \
    S2_3(1, 9, 13, 5, 3, aC);                                                  \
    S2_5(1, 12, 16, 6, 3, aC);                                                 \
    S2_3(1, 15, 21, 7, 3, aC);                                                 \
    S2_5(1, 18, 24, 8, 3, aC);                                                 \
    S2_5(4, 21, 29, 9, 5, aC);                                                 \
    S2_3(4, 26, 34, 10, 5, aC);                                                \
    S2_5(4, 31, 37, 11, 5, aC);                                                \
    S2_1(4, 36, 42, 12, 5, aC);                                                \
    S2_3(4, 41, 43, 13, 5, aC);                                                \
    S2_5(4, 46, 46, 14, 5, aC);                                                \
  }

__global__ void __launch_bounds__(128)
k_tp(const TPTab tab,
     const float* __restrict__ in1, const float* __restrict__ in2,
     const float* __restrict__ wt, const int* __restrict__ src,
     float* __restrict__ out)
{
  __shared__ __align__(16) float s_c[4][416];
  __shared__ __align__(16) float s_w[4][2 * 480];
  __shared__ __align__(16) float s_b[4][2 * 12];
  const int w = threadIdx.x >> 5;
  const int lane = threadIdx.x & 31;
  const int node = blockIdx.x * 4 + w;
  if (node >= N_NODES) return;
  float* cw = s_c[w];
  const uint32_t w_sm = smem_u32(&s_w[w][0]);
  const uint32_t b_sm = smem_u32(&s_b[w][0]);

  // hoist this lane's stage-1 cg + destinations (validated layout)
  const float A0c0 = tab.cgs[lane][0];
  const float A1c0 = tab.cgs[32 + lane][0];
  const float B0c0 = tab.cgs[64 + lane][0],  B0c1 = tab.cgs[64 + lane][1],  B0c2 = tab.cgs[64 + lane][2];
  const float B1c0 = tab.cgs[96 + lane][0],  B1c1 = tab.cgs[96 + lane][1],  B1c2 = tab.cgs[96 + lane][2];
  const float B2c0 = tab.cgs[128 + lane][0], B2c1 = tab.cgs[128 + lane][1], B2c2 = tab.cgs[128 + lane][2];
  const float C0c0 = tab.cgs[160 + lane][0], C0c1 = tab.cgs[160 + lane][1], C0c2 = tab.cgs[160 + lane][2],
              C0c3 = tab.cgs[160 + lane][3], C0c4 = tab.cgs[160 + lane][4];
  const float C1c0 = tab.cgs[192 + lane][0], C1c1 = tab.cgs[192 + lane][1], C1c2 = tab.cgs[192 + lane][2],
              C1c3 = tab.cgs[192 + lane][3], C1c4 = tab.cgs[192 + lane][4];
  const float C2c0 = tab.cgs[224 + lane][0], C2c1 = tab.cgs[224 + lane][1], C2c2 = tab.cgs[224 + lane][2],
              C2c3 = tab.cgs[224 + lane][3], C2c4 = tab.cgs[224 + lane][4];
  const int d0  = tab.dst[lane],        d1_ = tab.dst[32 + lane];
  const int d2_ = tab.dst[64 + lane],   d3_ = tab.dst[96 + lane];
  const int d4_ = tab.dst[128 + lane],  d5_ = tab.dst[160 + lane];
  const int d6_ = tab.dst[192 + lane],  d7_ = tab.dst[224 + lane];

  float acc[51];
#pragma unroll
  for (int k = 0; k < 51; ++k) acc[k] = 0.f;

  const int beg = g_row_ptr[node];
  const int end = g_row_ptr[node + 1];
  const int deg = end - beg;

  // lane-parallel preload of this node's edge ids + srcs (first 32)
  int myE = 0, myS = 0;
  if (lane < deg) { myE = g_edge_ids[beg + lane]; myS = src[myE]; }

  float a0[9], a1[9];

  if (deg > 0) {
    int e0, s0;
    GET_ES(0, e0, s0);
    ISSUE_CP(e0, 0);
    CPCOMMIT();
    LOAD_A(a0, s0);
  }

  int t = 0;
  while (t < deg) {
    EDGE_BODY(a0, a1, 0);
    ++t; if (t >= deg) break;
    EDGE_BODY(a1, a0, 1);
    ++t;
  }

  float* O = out + (size_t)node * OUT_DIM;
  STO(0, 1, 0);
  STO(32, 3, 1);
  STO(128, 5, 4);
  STO(288, 3, 9);
  STO(384, 1, 12);
  STO(416, 3, 13);
  STO(512, 5, 16);
  STO(672, 3, 21);
  STO(768, 5, 24);
  STO(928, 5, 29);
  STO(1088, 3, 34);
  STO(1184, 5, 37);
  STO(1344, 1, 42);
  STO(1376, 3, 43);
  STO(1472, 5, 46);
}

// ---------------------------------------------------------------------------
// Launch
// ---------------------------------------------------------------------------
extern "C" void kernel_launch(void* const* d_in, const int* in_sizes, int n_in,
                              void* d_out, int out_size) {
  const float* in1 = (const float*)d_in[0];
  const float* in2 = (const float*)d_in[1];
  const float* wt = (const float*)d_in[2];
  const int* src = (const int*)d_in[3];
  const int* dst = (const int*)d_in[4];
  float* out = (float*)d_out;

  TPTab tab;
  build_tab(tab);

  k_hist<<<(N_EDGES + 255) / 256, 256>>>(dst);
  k_scan<<<1, 1024>>>();
  k_scatter<<<(N_EDGES + 255) / 256, 256>>>(dst);
  k_tp<<<(N_NODES + 3) / 4, 128>>>(tab, in1, in2, wt, src, out);
}

// round 17
// speedup vs baseline: 1.4527x; 1.4527x over previous
#include <cuda_runtime.h>
#include <cstdint>
#include <cmath>
#include <cstring>

#define N_NODES 10000
#define N_EDGES 100000
#define IN1_DIM 288
#define IN2_DIM 9
#define W_DIM   480
#define OUT_DIM 1632

// slot tables for the warp-cooperative stage 1 (validated: rel_err 1.1e-7)
struct TPTab {
  float cgs[256][5];
  unsigned short dst[256];
};

// ---------------------------------------------------------------------------
// HOST: exact numpy default_rng(42) replay (validated R7..R16).
// ---------------------------------------------------------------------------
typedef unsigned __int128 u128_t;
struct HostPcg {
  u128_t st, inc;
  void step() {
    const u128_t M = ((u128_t)2549297995355413924ULL << 64) | 4865540595714422341ULL;
    st = st * M + inc;
  }
  uint64_t n64() {
    step();
    uint64_t hi = (uint64_t)(st >> 64), lo = (uint64_t)st;
    unsigned rot = (unsigned)(st >> 122);
    uint64_t x = hi ^ lo;
    return (x >> rot) | (x << ((64u - rot) & 63u));
  }
  double nd() { return (double)(n64() >> 11) * (1.0 / 9007199254740992.0); }
};

static const int tD1[15] = {1,1,1,3,3,3,3,3,3,5,5,5,5,5,5};
static const int tD2[15] = {1,3,5,1,3,3,3,5,5,1,3,3,5,5,5};
static const int tD3[15] = {1,3,5,3,1,3,5,3,5,5,3,5,1,3,5};
static const int tROWB[15] = {0,1,2,3,6,9,12,15,18,21,26,31,36,41,46};

static void build_tab(TPTab& T) {
  uint32_t pool[4];
  {
    uint32_t hc = 0x43b0d7e5u;
    auto h = [&hc](uint32_t v) -> uint32_t {
      v ^= hc; hc *= 0x931e8875u; v *= hc; v ^= v >> 16; return v;
    };
    auto mix = [](uint32_t x, uint32_t y) -> uint32_t {
      uint32_t r = (x * 0xca01f9ddu) - (y * 0x4973f715u);
      r ^= r >> 16;
      return r;
    };
    pool[0] = h(42u); pool[1] = h(0u); pool[2] = h(0u); pool[3] = h(0u);
    for (int s = 0; s < 4; ++s)
      for (int d = 0; d < 4; ++d)
        if (s != d) pool[d] = mix(pool[d], h(pool[s]));
  }
  uint64_t sw[4];
  {
    uint32_t hc = 0x8b51f9ddu;
    uint32_t w32[8];
    for (int i = 0; i < 8; ++i) {
      uint32_t v = pool[i & 3];
      v ^= hc; hc *= 0x58f38dedu; v *= hc; v ^= v >> 16;
      w32[i] = v;
    }
    for (int k = 0; k < 4; ++k)
      sw[k] = (uint64_t)w32[2 * k] | ((uint64_t)w32[2 * k + 1] << 32);
  }
  HostPcg g;
  {
    u128_t initstate = ((u128_t)sw[0] << 64) | sw[1];
    u128_t initseq   = ((u128_t)sw[2] << 64) | sw[3];
    g.st = 0; g.inc = (initseq << 1) | 1;
    g.step(); g.st += initstate; g.step();
  }

  double zwi[256], zfi[256]; uint64_t zki[256];
  {
    const double m = 4503599627370496.0, r = 3.6541528853610088;
    double f = exp(-0.5 * r * r);
    double v = r * f + sqrt(1.5707963267948966) * erfc(r * 0.7071067811865476);
    double q = v / f, dn = r, tn = r;
    zki[0] = (uint64_t)((dn / q) * m);  zki[1] = 0;
    zwi[0] = q / m;  zwi[255] = dn / m;
    zfi[0] = 1.0;    zfi[255] = f;
    for (int i = 254; i >= 1; --i) {
      dn = sqrt(-2.0 * log(v / dn + exp(-0.5 * dn * dn)));
      zki[i + 1] = (uint64_t)((dn / tn) * m);
      tn = dn;
      zfi[i] = exp(-0.5 * dn * dn);
      zwi[i] = dn / m;
    }
  }
  auto stdnorm = [&]() -> double {
    const double r = 3.6541528853610088, inv_r = 0.27366123732975828;
    for (;;) {
      uint64_t rr = g.n64();
      int idx = (int)(rr & 0xff);
      rr >>= 8;
      int sign = (int)(rr & 1);
      uint64_t rabs = (rr >> 1) & 0x000fffffffffffffULL;
      double x = (double)rabs * zwi[idx];
      if (sign) x = -x;
      if (rabs < zki[idx]) return x;
      if (idx == 0) {
        double xx, yy;
        do {
          xx = -inv_r * log1p(-g.nd());
          yy = -log1p(-g.nd());
        } while (yy + yy <= xx * xx);
        return ((rabs >> 8) & 1) ? -(r + xx) : (r + xx);
      }
      if ((zfi[idx - 1] - zfi[idx]) * g.nd() + zfi[idx] < exp(-0.5 * x * x))
        return x;
    }
  };

  float cgpw[15][125];
  for (int t = 0; t < 15; ++t) {
    int d1 = tD1[t], d2 = tD2[t], d3 = tD3[t], sz = d1 * d2 * d3;
    unsigned char mk[125]; int any = 0;
    for (int q = 0; q < sz; ++q) { mk[q] = (g.nd() < 0.3) ? 1 : 0; any |= mk[q]; }
    if (!any) mk[0] = 1;
    float pw = (float)(1.0 / sqrt((double)(d1 * d2)));
    for (int q = 0; q < sz; ++q) {
      float v = (float)stdnorm();
      cgpw[t][q] = mk[q] ? (v * pw) : 0.0f;
    }
  }

  memset(&T, 0, sizeof(T));
  for (int s = 0; s < 256; ++s) T.dst[s] = 408;
  const int gA[3] = {0, 3, 9};
  const int gB[6] = {1, 4, 5, 6, 10, 11};
  const int gC[6] = {2, 7, 8, 12, 13, 14};
  auto fill = [&](const int* grp, int ng, int slot) {
    for (int gi = 0; gi < ng; ++gi) {
      int t = grp[gi], d1 = tD1[t], d2 = tD2[t], d3 = tD3[t];
      for (int i = 0; i < d1; ++i)
        for (int k = 0; k < d3; ++k) {
          for (int j = 0; j < d2; ++j)
            T.cgs[slot][j] = cgpw[t][(i * d2 + j) * d3 + k];
          T.dst[slot] = (unsigned short)((tROWB[t] + i) * 8 + k);
          ++slot;
        }
    }
  };
  fill(gA, 3, 0); fill(gB, 6, 64); fill(gC, 6, 160);
}

// ---------------------------------------------------------------------------
// Device scratch. g_cursor zero at load; hist adds, scatter subs back to 0.
// ---------------------------------------------------------------------------
__device__ int g_row_ptr[N_NODES + 1];
__device__ int g_cursor[N_NODES];
__device__ int g_edge_ids[N_EDGES];

__global__ void k_hist(const int* __restrict__ dst) {
  int e = blockIdx.x * blockDim.x + threadIdx.x;
  if (e < N_EDGES) atomicAdd(&g_cursor[dst[e]], 1);
}

__global__ void k_scan() {
  __shared__ int s_wsum[32];
  __shared__ int s_carry;
  const int tid = threadIdx.x, lane = tid & 31, w = tid >> 5;
  if (tid == 0) s_carry = 0;
  __syncthreads();
  for (int base = 0; base < N_NODES; base += 1024) {
    int i = base + tid;
    int v = (i < N_NODES) ? g_cursor[i] : 0;
    int x = v;
#pragma unroll
    for (int d = 1; d < 32; d <<= 1) {
      int y = __shfl_up_sync(0xffffffffu, x, d);
      if (lane >= d) x += y;
    }
    if (lane == 31) s_wsum[w] = x;
    __syncthreads();
    if (w == 0) {
      int z = s_wsum[lane];
#pragma unroll
      for (int d = 1; d < 32; d <<= 1) {
        int y = __shfl_up_sync(0xffffffffu, z, d);
        if (lane >= d) z += y;
      }
      s_wsum[lane] = z;
    }
    __syncthreads();
    int warp_excl = (w == 0) ? 0 : s_wsum[w - 1];
    int excl = s_carry + warp_excl + (x - v);
    if (i < N_NODES) g_row_ptr[i] = excl;
    __syncthreads();
    if (tid == 0) s_carry += s_wsum[31];
    __syncthreads();
  }
  if (tid == 0) g_row_ptr[N_NODES] = s_carry;
}

__global__ void k_scatter(const int* __restrict__ dst) {
  int e = blockIdx.x * blockDim.x + threadIdx.x;
  if (e < N_EDGES) {
    int d = dst[e];
    int pos = atomicSub(&g_cursor[d], 1) - 1;
    g_edge_ids[g_row_ptr[d] + pos] = e;
  }
}

// ---------------------------------------------------------------------------
// Main kernel: warp per node, R14 register pipeline, cg table in block smem.
// Per edge: issue w (current) first, prefetch a/b (next edge), stage1 reads
// cg from smem (stride-5 layout: gcd(5,32)=1 -> conflict-free), stage2 FMA.
// ---------------------------------------------------------------------------
#define S2_1(AB, RB, KB, WI, DD, AA) { float t0 = 0.f;                         \
  _Pragma("unroll") for (int i = 0; i < (DD); ++i)                             \
    t0 = fmaf(AA[(AB) + i], cw[((RB) + i) * 8], t0);                           \
  acc[(KB)] = fmaf(wv[(WI)], t0, acc[(KB)]); }

#define S2_3(AB, RB, KB, WI, DD, AA) { float t0 = 0.f, t1 = 0.f, t2 = 0.f;     \
  _Pragma("unroll") for (int i = 0; i < (DD); ++i) {                           \
    float4 cv = *(const float4*)&cw[((RB) + i) * 8];                           \
    float ai = AA[(AB) + i];                                                   \
    t0 = fmaf(ai, cv.x, t0); t1 = fmaf(ai, cv.y, t1); t2 = fmaf(ai, cv.z, t2); } \
  acc[(KB)]     = fmaf(wv[(WI)], t0, acc[(KB)]);                               \
  acc[(KB) + 1] = fmaf(wv[(WI)], t1, acc[(KB) + 1]);                           \
  acc[(KB) + 2] = fmaf(wv[(WI)], t2, acc[(KB) + 2]); }

#define S2_5(AB, RB, KB, WI, DD, AA) {                                         \
  float t0 = 0.f, t1 = 0.f, t2 = 0.f, t3 = 0.f, t4 = 0.f;                      \
  _Pragma("unroll") for (int i = 0; i < (DD); ++i) {                           \
    float4 cv = *(const float4*)&cw[((RB) + i) * 8];                           \
    float c4 = cw[((RB) + i) * 8 + 4];                                         \
    float ai = AA[(AB) + i];                                                   \
    t0 = fmaf(ai, cv.x, t0); t1 = fmaf(ai, cv.y, t1); t2 = fmaf(ai, cv.z, t2); \
    t3 = fmaf(ai, cv.w, t3); t4 = fmaf(ai, c4, t4); }                          \
  acc[(KB)]     = fmaf(wv[(WI)], t0, acc[(KB)]);                               \
  acc[(KB) + 1] = fmaf(wv[(WI)], t1, acc[(KB) + 1]);                           \
  acc[(KB) + 2] = fmaf(wv[(WI)], t2, acc[(KB) + 2]);                           \
  acc[(KB) + 3] = fmaf(wv[(WI)], t3, acc[(KB) + 3]);                           \
  acc[(KB) + 4] = fmaf(wv[(WI)], t4, acc[(KB) + 4]); }

#define STO(OFF, DD, KB)                                                       \
  _Pragma("unroll") for (int k = 0; k < (DD); ++k)                             \
    O[(OFF) + lane * (DD) + k] = acc[(KB) + k];

#define LOAD_A(AA, S)                                                          \
  { const float* A_ = in1 + (size_t)(S) * IN1_DIM;                             \
    AA[0] = A_[lane];                                                          \
    { const float* p = A_ + 32 + lane * 3;  AA[1] = p[0]; AA[2] = p[1]; AA[3] = p[2]; } \
    { const float* p = A_ + 128 + lane * 5; AA[4] = p[0]; AA[5] = p[1]; AA[6] = p[2]; AA[7] = p[3]; AA[8] = p[4]; } }

#define LOAD_B(BB, E)                                                          \
  { const float* B_ = in2 + (size_t)(E) * IN2_DIM;                             \
    _Pragma("unroll") for (int j = 0; j < 9; ++j) BB[j] = B_[j]; }

#define LOAD_W(WW, E)                                                          \
  { const float* W_ = wt + (size_t)(E) * W_DIM + lane;                         \
    _Pragma("unroll") for (int q = 0; q < 15; ++q) WW[q] = W_[q * 32]; }

// edge index T -> (edge id, src): shfl broadcast for T<32, direct load beyond
#define GET_ES(T, EV, SV)                                                      \
  if ((T) < 32) {                                                              \
    EV = __shfl_sync(0xffffffffu, myE, (T));                                   \
    SV = __shfl_sync(0xffffffffu, myS, (T));                                   \
  } else {                                                                     \
    EV = g_edge_ids[beg + (T)];                                                \
    SV = src[EV];                                                              \
  }

// One pipelined edge: w(current) issued first, a/b(next) prefetched, stage1
// reads cg from smem, stage2 consumes aC + wv.
#define EDGE_BODY(aC, bC, aN, bN)                                              \
  {                                                                            \
    float wv[15];                                                              \
    LOAD_W(wv, eCur);                                                          \
    if (t + 1 < deg) {                                                         \
      GET_ES(t + 1, eN, sN);                                                   \
      LOAD_A(aN, sN);                                                          \
      LOAD_B(bN, eN);                                                          \
    }                                                                          \
    __syncwarp();                                                              \
    {                                                                          \
      const float* G0 = &s_cg[lane * 5];                                       \
      const float* G1 = &s_cg[(32 + lane) * 5];                                \
      const float* G2 = &s_cg[(64 + lane) * 5];                                \
      const float* G3 = &s_cg[(96 + lane) * 5];                                \
      const float* G4 = &s_cg[(128 + lane) * 5];                               \
      const float* G5 = &s_cg[(160 + lane) * 5];                               \
      const float* G6 = &s_cg[(192 + lane) * 5];                               \
      const float* G7 = &s_cg[(224 + lane) * 5];                               \
      cw[d0]  = G0[0] * bC[0];                                                 \
      cw[d1_] = G1[0] * bC[0];                                                 \
      cw[d2_] = fmaf(G2[2], bC[3], fmaf(G2[1], bC[2], G2[0] * bC[1]));         \
      cw[d3_] = fmaf(G3[2], bC[3], fmaf(G3[1], bC[2], G3[0] * bC[1]));         \
      cw[d4_] = fmaf(G4[2], bC[3], fmaf(G4[1], bC[2], G4[0] * bC[1]));         \
      cw[d5_] = fmaf(G5[4], bC[8], fmaf(G5[3], bC[7], fmaf(G5[2], bC[6], fmaf(G5[1], bC[5], G5[0] * bC[4])))); \
      cw[d6_] = fmaf(G6[4], bC[8], fmaf(G6[3], bC[7], fmaf(G6[2], bC[6], fmaf(G6[1], bC[5], G6[0] * bC[4])))); \
      cw[d7_] = fmaf(G7[4], bC[8], fmaf(G7[3], bC[7], fmaf(G7[2], bC[6], fmaf(G7[1], bC[5], G7[0] * bC[4])))); \
    }                                                                          \
    __syncwarp();                                                              \
    S2_1(0, 0, 0, 0, 1, aC);                                                   \
    S2_3(0, 1, 1, 1, 1, aC);                                                   \
    S2_5(0, 2, 4, 2, 1, aC);                                                   \
    S2_3(1, 3, 9, 3, 3, aC);                                                   \
    S2_1(1, 6, 12, 4, 3, aC);                                                  \
    S2_3(1, 9, 13, 5, 3, aC);                                                  \
    S2_5(1, 12, 16, 6, 3, aC);                                                 \
    S2_3(1, 15, 21, 7, 3, aC);                                                 \
    S2_5(1, 18, 24, 8, 3, aC);                                                 \
    S2_5(4, 21, 29, 9, 5, aC);                                                 \
    S2_3(4, 26, 34, 10, 5, aC);                                                \
    S2_5(4, 31, 37, 11, 5, aC);                                                \
    S2_1(4, 36, 42, 12, 5, aC);                                                \
    S2_3(4, 41, 43, 13, 5, aC);                                                \
    S2_5(4, 46, 46, 14, 5, aC);                                                \
    eCur = eN; sCur = sN;                                                      \
  }

__global__ void __launch_bounds__(128, 3)
k_tp(const TPTab tab,
     const float* __restrict__ in1, const float* __restrict__ in2,
     const float* __restrict__ wt, const int* __restrict__ src,
     float* __restrict__ out)
{
  __shared__ __align__(16) float s_c[4][416];
  __shared__ float s_cg[256 * 5];
  const int w = threadIdx.x >> 5;
  const int lane = threadIdx.x & 31;
  const int node = blockIdx.x * 4 + w;
  float* cw = s_c[w];

  // block-cooperative copy of cg table (param const bank -> smem), once
  {
    const float* flat = &tab.cgs[0][0];
    for (int i = threadIdx.x; i < 256 * 5; i += 128) s_cg[i] = flat[i];
  }
  __syncthreads();
  if (node >= N_NODES) return;

  // dst indices stay in registers (8 ints, loop-invariant)
  const int d0  = tab.dst[lane],        d1_ = tab.dst[32 + lane];
  const int d2_ = tab.dst[64 + lane],   d3_ = tab.dst[96 + lane];
  const int d4_ = tab.dst[128 + lane],  d5_ = tab.dst[160 + lane];
  const int d6_ = tab.dst[192 + lane],  d7_ = tab.dst[224 + lane];

  float acc[51];
#pragma unroll
  for (int k = 0; k < 51; ++k) acc[k] = 0.f;

  const int beg = g_row_ptr[node];
  const int end = g_row_ptr[node + 1];
  const int deg = end - beg;

  // lane-parallel preload of this node's edge ids + srcs (first 32)
  int myE = 0, myS = 0;
  if (lane < deg) { myE = g_edge_ids[beg + lane]; myS = src[myE]; }

  float a0[9], b0[9], a1[9], b1[9];
  int eCur = 0, sCur = 0, eN = 0, sN = 0;

  if (deg > 0) {
    GET_ES(0, eCur, sCur);
    LOAD_A(a0, sCur); LOAD_B(b0, eCur);
  }

  int t = 0;
  while (t < deg) {
    EDGE_BODY(a0, b0, a1, b1);
    ++t; if (t >= deg) break;
    EDGE_BODY(a1, b1, a0, b0);
    ++t;
  }

  float* O = out + (size_t)node * OUT_DIM;
  STO(0, 1, 0);
  STO(32, 3, 1);
  STO(128, 5, 4);
  STO(288, 3, 9);
  STO(384, 1, 12);
  STO(416, 3, 13);
  STO(512, 5, 16);
  STO(672, 3, 21);
  STO(768, 5, 24);
  STO(928, 5, 29);
  STO(1088, 3, 34);
  STO(1184, 5, 37);
  STO(1344, 1, 42);
  STO(1376, 3, 43);
  STO(1472, 5, 46);
}

// ---------------------------------------------------------------------------
// Launch
// ---------------------------------------------------------------------------
extern "C" void kernel_launch(void* const* d_in, const int* in_sizes, int n_in,
                              void* d_out, int out_size) {
  const float* in1 = (const float*)d_in[0];
  const float* in2 = (const float*)d_in[1];
  const float* wt = (const float*)d_in[2];
  const int* src = (const int*)d_in[3];
  const int* dst = (const int*)d_in[4];
  float* out = (float*)d_out;

  TPTab tab;
  build_tab(tab);

  k_hist<<<(N_EDGES + 255) / 256, 256>>>(dst);
  k_scan<<<1, 1024>>>();
  k_scatter<<<(N_EDGES + 255) / 256, 256>>>(dst);
  k_tp<<<(N_NODES + 3) / 4, 128>>>(tab, in1, in2, wt, src, out);
}